// round 10
// baseline (speedup 1.0000x reference)
#include <cuda_runtime.h>
#include <stdint.h>

#define B_ROWS 8192
#define D_DIM  512
#define N_OFF  16

struct OffArgs { int off[N_OFF]; };

// 16-bit per-row fixed-point item plane.
// Element (row, c, k, lane) = items[row*512 + c*128 + 4*lane + k] is encoded
// e16 = round(v * 32767/rowmax) + 2^15  (unsigned, in [1, 65535]).
// g_pk: uint4 at (row*2 + h)*32 + lane, h in {0,1}:
//   word0 = chunk 2h   e0|e1<<16, word1 = chunk 2h   e2|e3<<16,
//   word2 = chunk 2h+1 e0|e1<<16, word3 = chunk 2h+1 e2|e3<<16.
// g_step: per-row dequant scale = rowmax / 32767.
__device__ uint4 g_pk[B_ROWS * 64];    // 8 MB
__device__ float g_step[B_ROWS];

#define MAGIC16 8421376.0f   // 2^23 + 2^15
#define FULL 0xffffffffu

// ---------------------------------------------------------------------------
// Prepass: warp per item row. rowmax -> scale, magic-FMA quantize, pack pairs.
// Trigger fires FIRST so the dependent main kernel launches while pack runs;
// main's gridDependencySynchronize still waits for full pack completion, so
// g_pk/g_step visibility is unaffected by the early trigger.
// ---------------------------------------------------------------------------
__global__ __launch_bounds__(256) void ibns_pack_kernel(const float* __restrict__ items)
{
    cudaTriggerProgrammaticLaunchCompletion();

    const int row  = (blockIdx.x * 256 + threadIdx.x) >> 5;
    const int lane = threadIdx.x & 31;

    float4 v[4];
#pragma unroll
    for (int c = 0; c < 4; c++)
        v[c] = *reinterpret_cast<const float4*>(
            items + (size_t)row * D_DIM + 128 * c + 4 * lane);

    float m = 0.f;
#pragma unroll
    for (int c = 0; c < 4; c++) {
        m = fmaxf(m, fmaxf(fmaxf(fabsf(v[c].x), fabsf(v[c].y)),
                           fmaxf(fabsf(v[c].z), fabsf(v[c].w))));
    }
    m = fmaxf(m, __shfl_xor_sync(FULL, m, 16));
    m = fmaxf(m, __shfl_xor_sync(FULL, m, 8));
    m = fmaxf(m, __shfl_xor_sync(FULL, m, 4));
    m = fmaxf(m, __shfl_xor_sync(FULL, m, 2));
    m = fmaxf(m, __shfl_xor_sync(FULL, m, 1));

    const float inv = 32767.0f / m;
    if (lane == 0) g_step[row] = m / 32767.0f;

    uint32_t u[4][4];   // bits[15:0] = e16 after magic-FMA
#pragma unroll
    for (int c = 0; c < 4; c++) {
        const float* vc = &v[c].x;
#pragma unroll
        for (int k = 0; k < 4; k++)
            u[c][k] = __float_as_uint(fmaf(vc[k], inv, MAGIC16));
    }

#pragma unroll
    for (int w = 0; w < 2; w++) {
        uint4 P;
        P.x = __byte_perm(u[2*w  ][0], u[2*w  ][1], 0x5410);
        P.y = __byte_perm(u[2*w  ][2], u[2*w  ][3], 0x5410);
        P.z = __byte_perm(u[2*w+1][0], u[2*w+1][1], 0x5410);
        P.w = __byte_perm(u[2*w+1][2], u[2*w+1][3], 0x5410);
        g_pk[(row * 2 + w) * 32 + lane] = P;
    }
}

// One 4-element chunk: two packed words -> 4 magic floats (1 PRMT each),
// FMA against q with the bias pre-folded into rc = -MAGIC16 * sum(qc).
__device__ __forceinline__ float chunk_dot16(float4 qc, uint32_t e01, uint32_t e23,
                                             float rc)
{
    float t;
    t = fmaf(qc.x, __uint_as_float(__byte_perm(e01, 0x4B000000u, 0x7610)), rc);
    t = fmaf(qc.y, __uint_as_float(__byte_perm(e01, 0x4B000000u, 0x7632)), t);
    t = fmaf(qc.z, __uint_as_float(__byte_perm(e23, 0x4B000000u, 0x7610)), t);
    t = fmaf(qc.w, __uint_as_float(__byte_perm(e23, 0x4B000000u, 0x7632)), t);
    return t;
}

// ---------------------------------------------------------------------------
// Main kernel: TEAM of 2 warps per query row; warp h owns D-half h.
// PDL: q loads + rc run before gridDependencySynchronize; the g_pk/g_step
// gather waits for the pack grid. Item gathers use __ldcg (L2-only).
// ---------------------------------------------------------------------------
__global__ __launch_bounds__(256, 4) void ibns_kernel(
    const float* __restrict__ q,
    float* __restrict__ out,
    OffArgs oa)
{
    __shared__ float red[4 * 32];                       // per-team combine slots

    const int team = threadIdx.x >> 6;                  // 0..3 within CTA
    const int gw   = blockIdx.x * 4 + team;             // query row
    const int h    = (threadIdx.x >> 5) & 1;            // D-half
    const int lane = threadIdx.x & 31;

    // ---- Phase 1: independent of pack kernel ----
    const float4* qr = reinterpret_cast<const float4*>(
        q + (size_t)gw * D_DIM + 256 * h);
    float4 qv[2];
    qv[0] = qr[lane];
    qv[1] = qr[lane + 32];

    float rc[2];
#pragma unroll
    for (int c = 0; c < 2; c++)
        rc[c] = -MAGIC16 * (qv[c].x + qv[c].y + qv[c].z + qv[c].w);

    // ---- Wait for pack grid (g_pk / g_step visible after this) ----
    cudaGridDependencySynchronize();

    // Per-row dequant steps (lane n holds row n's, n < 16) — issue early.
    float stepv = 0.f;
    if (lane < N_OFF)
        stepv = g_step[(gw + oa.off[lane]) & (B_ROWS - 1)];

    float s[N_OFF];

#pragma unroll
    for (int p = 0; p < 2; p++) {       // 2 batches of 8 rows, 8 LDG.128 each
        uint4 P[8];
#pragma unroll
        for (int r = 0; r < 8; r++) {
            const int n = 8 * p + r;
            const int j = (gw + oa.off[n]) & (B_ROWS - 1);
            P[r] = __ldcg(&g_pk[(j * 2 + h) * 32 + lane]);
        }
#pragma unroll
        for (int r = 0; r < 8; r++) {
            float acc;
            acc  = chunk_dot16(qv[0], P[r].x, P[r].y, rc[0]);
            acc += chunk_dot16(qv[1], P[r].z, P[r].w, rc[1]);
            s[8 * p + r] = acc;
        }
    }

    // Packed tree reduction: 31 SHFL. After L5, lane l holds the 32-lane sum
    // of s[n(l)] with n(l) = b4 | (b3<<1) | (b2<<2) | (b1<<3) (bit0 dups).
    float v8[8];
#pragma unroll
    for (int i = 0; i < 8; i++) {
        float a = s[2*i],  b = s[2*i+1];
        a += __shfl_xor_sync(FULL, a, 16);
        b += __shfl_xor_sync(FULL, b, 16);
        v8[i] = (lane & 16) ? b : a;
    }
    float v4[4];
#pragma unroll
    for (int i = 0; i < 4; i++) {
        float a = v8[2*i], b = v8[2*i+1];
        a += __shfl_xor_sync(FULL, a, 8);
        b += __shfl_xor_sync(FULL, b, 8);
        v4[i] = (lane & 8) ? b : a;
    }
    float v2[2];
#pragma unroll
    for (int i = 0; i < 2; i++) {
        float a = v4[2*i], b = v4[2*i+1];
        a += __shfl_xor_sync(FULL, a, 4);
        b += __shfl_xor_sync(FULL, b, 4);
        v2[i] = (lane & 4) ? b : a;
    }
    float y;
    {
        float a = v2[0], b = v2[1];
        a += __shfl_xor_sync(FULL, a, 2);
        b += __shfl_xor_sync(FULL, b, 2);
        y = (lane & 2) ? b : a;
    }
    y += __shfl_xor_sync(FULL, y, 1);

    // Cross-warp combine: warp h=0 publishes, warp h=1 finishes.
    if (h == 0) red[team * 32 + lane] = y;
    __syncthreads();

    if (h == 1) {
        y += red[team * 32 + lane];

        const int nl = ((lane >> 4) & 1) | ((lane >> 2) & 2)
                     | (lane & 4) | ((lane << 2) & 8);
        const float S = y * __shfl_sync(FULL, stepv, nl);

        // Lane-parallel softmax (each of 16 values duplicated 2x).
        float mx = S;
        mx = fmaxf(mx, __shfl_xor_sync(FULL, mx, 16));
        mx = fmaxf(mx, __shfl_xor_sync(FULL, mx, 8));
        mx = fmaxf(mx, __shfl_xor_sync(FULL, mx, 4));
        mx = fmaxf(mx, __shfl_xor_sync(FULL, mx, 2));
        mx = fmaxf(mx, __shfl_xor_sync(FULL, mx, 1));

        float e = __expf((S - mx) * 10.0f);
        float tot = e;
        tot += __shfl_xor_sync(FULL, tot, 16);
        tot += __shfl_xor_sync(FULL, tot, 8);
        tot += __shfl_xor_sync(FULL, tot, 4);
        tot += __shfl_xor_sync(FULL, tot, 2);
        tot += __shfl_xor_sync(FULL, tot, 1);   // = 2 * denom

        if (lane == 0)                           // n(0) = 0: the positive
            out[gw] = e * 2.0f / tot;
    }
}

// ---------------------------------------------------------------------------
// Host-side exact replication of numpy's
//   np.random.default_rng(0).choice(np.arange(1, 8192), size=15, replace=False)
// SeedSequence(0) -> PCG64 (XSL-RR 128/64) -> Generator.choice Floyd's algorithm
// with hash set + final _shuffle_int. Deterministic, stateless, no allocation.
// ---------------------------------------------------------------------------
namespace ibns_rng {

typedef unsigned __int128 u128;

struct Pcg {
    u128 state, inc;
    int has32;
    uint32_t buf;
};

static inline uint64_t rotr64(uint64_t x, uint32_t r) {
    return (x >> r) | (x << ((64u - r) & 63u));
}

static const u128 PCG_MULT = (((u128)2549297995355413924ULL) << 64) | 4865540595714422341ULL;

static inline uint64_t pcg_next64(Pcg* p) {
    p->state = p->state * PCG_MULT + p->inc;
    uint64_t hi = (uint64_t)(p->state >> 64);
    uint64_t lo = (uint64_t)p->state;
    uint32_t rot = (uint32_t)(p->state >> 122);
    return rotr64(hi ^ lo, rot);
}

static inline uint32_t pcg_next32(Pcg* p) {
    if (p->has32) { p->has32 = 0; return p->buf; }
    uint64_t v = pcg_next64(p);
    p->has32 = 1;
    p->buf = (uint32_t)(v >> 32);
    return (uint32_t)v;
}

static inline uint32_t lemire32(Pcg* p, uint32_t rng) {
    if (rng == 0) return 0;
    const uint32_t rng_excl = rng + 1u;
    uint64_t m = (uint64_t)pcg_next32(p) * (uint64_t)rng_excl;
    uint32_t leftover = (uint32_t)m;
    if (leftover < rng_excl) {
        const uint32_t threshold = (0xFFFFFFFFu - rng) % rng_excl;
        while (leftover < threshold) {
            m = (uint64_t)pcg_next32(p) * (uint64_t)rng_excl;
            leftover = (uint32_t)m;
        }
    }
    return (uint32_t)(m >> 32);
}

static const uint32_t INIT_A = 0x43b0d7e5u, MULT_A = 0x931e8875u;
static const uint32_t INIT_B = 0x8b51f9ddu, MULT_B = 0x58f38dedu;
static const uint32_t MIX_L  = 0xca01f9ddu, MIX_R  = 0x4973f715u;

static inline uint32_t hashmix(uint32_t v, uint32_t* hc) {
    v ^= *hc;
    *hc = (uint32_t)(*hc * MULT_A);
    v = (uint32_t)(v * *hc);
    v ^= v >> 16;
    return v;
}
static inline uint32_t mixfn(uint32_t x, uint32_t y) {
    uint32_t r = (uint32_t)(MIX_L * x - MIX_R * y);
    r ^= r >> 16;
    return r;
}

static void compute_offsets(int* off16) {
    uint32_t pool[4];
    uint32_t hc = INIT_A;
    pool[0] = hashmix(0u, &hc);
    pool[1] = hashmix(0u, &hc);
    pool[2] = hashmix(0u, &hc);
    pool[3] = hashmix(0u, &hc);
    for (int i_src = 0; i_src < 4; i_src++)
        for (int i_dst = 0; i_dst < 4; i_dst++)
            if (i_src != i_dst)
                pool[i_dst] = mixfn(pool[i_dst], hashmix(pool[i_src], &hc));

    uint32_t w[8];
    hc = INIT_B;
    for (int i = 0; i < 8; i++) {
        uint32_t dv = pool[i & 3];
        dv ^= hc;
        hc = (uint32_t)(hc * MULT_B);
        dv = (uint32_t)(dv * hc);
        dv ^= dv >> 16;
        w[i] = dv;
    }
    uint64_t val[4];
    for (int k = 0; k < 4; k++)
        val[k] = (uint64_t)w[2 * k] | ((uint64_t)w[2 * k + 1] << 32);

    u128 initstate = (((u128)val[0]) << 64) | val[1];
    u128 initseq   = (((u128)val[2]) << 64) | val[3];
    Pcg p;
    p.has32 = 0; p.buf = 0;
    p.state = 0;
    p.inc = (initseq << 1) | 1;
    p.state = p.state * PCG_MULT + p.inc;
    p.state += initstate;
    p.state = p.state * PCG_MULT + p.inc;

    const int pop_size = 8191, size = 15;
    const uint64_t NONE = ~(uint64_t)0;
    uint64_t hset[32];
    for (int i = 0; i < 32; i++) hset[i] = NONE;
    int64_t idx[15];
    for (int j = pop_size - size; j < pop_size; j++) {
        uint64_t v = (uint64_t)lemire32(&p, (uint32_t)j);
        uint32_t loc = (uint32_t)(v & 31u);
        while (hset[loc] != NONE && hset[loc] != v) loc = (loc + 1u) & 31u;
        if (hset[loc] == NONE) {
            hset[loc] = v;
            idx[j - (pop_size - size)] = (int64_t)v;
        } else {
            loc = (uint32_t)((uint32_t)j & 31u);
            while (hset[loc] != NONE) loc = (loc + 1u) & 31u;
            hset[loc] = (uint64_t)j;
            idx[j - (pop_size - size)] = (int64_t)j;
        }
    }
    for (int i = size - 1; i >= 1; i--) {
        uint32_t j = lemire32(&p, (uint32_t)i);
        int64_t t = idx[j]; idx[j] = idx[i]; idx[i] = t;
    }

    off16[0] = 0;
    for (int n = 0; n < 15; n++) off16[n + 1] = (int)(idx[n] + 1);
}

} // namespace ibns_rng

extern "C" void kernel_launch(void* const* d_in, const int* in_sizes, int n_in,
                              void* d_out, int out_size) {
    (void)in_sizes; (void)n_in; (void)out_size;
    OffArgs oa;
    ibns_rng::compute_offsets(oa.off);

    const float* q     = (const float*)d_in[0];
    const float* items = (const float*)d_in[1];
    float* out         = (float*)d_out;

    // Pack (primary) — triggers PDL completion at CTA start.
    ibns_pack_kernel<<<B_ROWS / 8, 256>>>(items);

    // Main (secondary) with Programmatic Dependent Launch: starts while pack
    // is still running; it gridDependencySynchronize()s before the gathers.
    cudaLaunchConfig_t cfg = {};
    cfg.gridDim  = dim3(B_ROWS / 4);
    cfg.blockDim = dim3(256);
    cfg.dynamicSmemBytes = 0;
    cfg.stream = 0;
    cudaLaunchAttribute attr[1];
    attr[0].id = cudaLaunchAttributeProgrammaticStreamSerialization;
    attr[0].val.programmaticStreamSerializationAllowed = 1;
    cfg.attrs = attr;
    cfg.numAttrs = 1;
    cudaError_t e = cudaLaunchKernelEx(&cfg, ibns_kernel, q, out, oa);
    if (e != cudaSuccess) {
        // Fallback: plain serialized launch (still correct).
        ibns_kernel<<<B_ROWS / 4, 256>>>(q, out, oa);
    }
}

// round 11
// speedup vs baseline: 1.0138x; 1.0138x over previous
#include <cuda_runtime.h>
#include <stdint.h>

#define B_ROWS 8192
#define D_DIM  512
#define N_OFF  16

#define PACK_CTAS  592               // one full wave: 148 SMs x 4 CTAs
#define PACK_WARPS (PACK_CTAS * 8)   // 4736 warps, 2 rows each covers 8192

struct OffArgs { int off[N_OFF]; };

// 16-bit per-row fixed-point item plane.
// Element (row, c, k, lane) = items[row*512 + c*128 + 4*lane + k] is encoded
// e16 = round(v * 32767/rowmax) + 2^15  (unsigned, in [1, 65535]).
// g_pk: uint4 at (row*2 + h)*32 + lane, h in {0,1}:
//   word0 = chunk 2h   e0|e1<<16, word1 = chunk 2h   e2|e3<<16,
//   word2 = chunk 2h+1 e0|e1<<16, word3 = chunk 2h+1 e2|e3<<16.
// g_step: per-row dequant scale = rowmax / 32767.
__device__ uint4 g_pk[B_ROWS * 64];    // 8 MB
__device__ float g_step[B_ROWS];

#define MAGIC16 8421376.0f   // 2^23 + 2^15
#define FULL 0xffffffffu

// ---------------------------------------------------------------------------
// Prepass: ONE-WAVE grid (592 CTAs, 4/SM at 256thr) so all pack CTAs are
// resident immediately and the PDL secondary (main) co-resides beside them
// (1024 + 1024 threads per SM). Each warp packs rows w and w + PACK_WARPS.
// Early trigger lets main's q-phase overlap the whole pack.
// ---------------------------------------------------------------------------
__global__ __launch_bounds__(256, 4) void ibns_pack_kernel(const float* __restrict__ items)
{
    cudaTriggerProgrammaticLaunchCompletion();

    const int warp = (blockIdx.x * 256 + threadIdx.x) >> 5;
    const int lane = threadIdx.x & 31;

    for (int row = warp; row < B_ROWS; row += PACK_WARPS) {
        float4 v[4];
#pragma unroll
        for (int c = 0; c < 4; c++)
            v[c] = *reinterpret_cast<const float4*>(
                items + (size_t)row * D_DIM + 128 * c + 4 * lane);

        float m = 0.f;
#pragma unroll
        for (int c = 0; c < 4; c++) {
            m = fmaxf(m, fmaxf(fmaxf(fabsf(v[c].x), fabsf(v[c].y)),
                               fmaxf(fabsf(v[c].z), fabsf(v[c].w))));
        }
        m = fmaxf(m, __shfl_xor_sync(FULL, m, 16));
        m = fmaxf(m, __shfl_xor_sync(FULL, m, 8));
        m = fmaxf(m, __shfl_xor_sync(FULL, m, 4));
        m = fmaxf(m, __shfl_xor_sync(FULL, m, 2));
        m = fmaxf(m, __shfl_xor_sync(FULL, m, 1));

        const float inv = 32767.0f / m;
        if (lane == 0) g_step[row] = m / 32767.0f;

        uint32_t u[4][4];   // bits[15:0] = e16 after magic-FMA
#pragma unroll
        for (int c = 0; c < 4; c++) {
            const float* vc = &v[c].x;
#pragma unroll
            for (int k = 0; k < 4; k++)
                u[c][k] = __float_as_uint(fmaf(vc[k], inv, MAGIC16));
        }

#pragma unroll
        for (int w = 0; w < 2; w++) {
            uint4 P;
            P.x = __byte_perm(u[2*w  ][0], u[2*w  ][1], 0x5410);
            P.y = __byte_perm(u[2*w  ][2], u[2*w  ][3], 0x5410);
            P.z = __byte_perm(u[2*w+1][0], u[2*w+1][1], 0x5410);
            P.w = __byte_perm(u[2*w+1][2], u[2*w+1][3], 0x5410);
            g_pk[(row * 2 + w) * 32 + lane] = P;
        }
    }
}

// One 4-element chunk: two packed words -> 4 magic floats (1 PRMT each),
// FMA against q with the bias pre-folded into rc = -MAGIC16 * sum(qc).
__device__ __forceinline__ float chunk_dot16(float4 qc, uint32_t e01, uint32_t e23,
                                             float rc)
{
    float t;
    t = fmaf(qc.x, __uint_as_float(__byte_perm(e01, 0x4B000000u, 0x7610)), rc);
    t = fmaf(qc.y, __uint_as_float(__byte_perm(e01, 0x4B000000u, 0x7632)), t);
    t = fmaf(qc.z, __uint_as_float(__byte_perm(e23, 0x4B000000u, 0x7610)), t);
    t = fmaf(qc.w, __uint_as_float(__byte_perm(e23, 0x4B000000u, 0x7632)), t);
    return t;
}

// ---------------------------------------------------------------------------
// Main kernel: TEAM of 2 warps per query row; warp h owns D-half h.
// PDL: q loads + rc run before gridDependencySynchronize; the g_pk/g_step
// gather waits for the pack grid. Item gathers use __ldcg (L2-only).
// ---------------------------------------------------------------------------
__global__ __launch_bounds__(256, 4) void ibns_kernel(
    const float* __restrict__ q,
    float* __restrict__ out,
    OffArgs oa)
{
    __shared__ float red[4 * 32];                       // per-team combine slots

    const int team = threadIdx.x >> 6;                  // 0..3 within CTA
    const int gw   = blockIdx.x * 4 + team;             // query row
    const int h    = (threadIdx.x >> 5) & 1;            // D-half
    const int lane = threadIdx.x & 31;

    // ---- Phase 1: independent of pack kernel ----
    const float4* qr = reinterpret_cast<const float4*>(
        q + (size_t)gw * D_DIM + 256 * h);
    float4 qv[2];
    qv[0] = qr[lane];
    qv[1] = qr[lane + 32];

    float rc[2];
#pragma unroll
    for (int c = 0; c < 2; c++)
        rc[c] = -MAGIC16 * (qv[c].x + qv[c].y + qv[c].z + qv[c].w);

    // ---- Wait for pack grid (g_pk / g_step visible after this) ----
    cudaGridDependencySynchronize();

    // Per-row dequant steps (lane n holds row n's, n < 16) — issue early.
    float stepv = 0.f;
    if (lane < N_OFF)
        stepv = g_step[(gw + oa.off[lane]) & (B_ROWS - 1)];

    float s[N_OFF];

#pragma unroll
    for (int p = 0; p < 2; p++) {       // 2 batches of 8 rows, 8 LDG.128 each
        uint4 P[8];
#pragma unroll
        for (int r = 0; r < 8; r++) {
            const int n = 8 * p + r;
            const int j = (gw + oa.off[n]) & (B_ROWS - 1);
            P[r] = __ldcg(&g_pk[(j * 2 + h) * 32 + lane]);
        }
#pragma unroll
        for (int r = 0; r < 8; r++) {
            float acc;
            acc  = chunk_dot16(qv[0], P[r].x, P[r].y, rc[0]);
            acc += chunk_dot16(qv[1], P[r].z, P[r].w, rc[1]);
            s[8 * p + r] = acc;
        }
    }

    // Packed tree reduction: 31 SHFL. After L5, lane l holds the 32-lane sum
    // of s[n(l)] with n(l) = b4 | (b3<<1) | (b2<<2) | (b1<<3) (bit0 dups).
    float v8[8];
#pragma unroll
    for (int i = 0; i < 8; i++) {
        float a = s[2*i],  b = s[2*i+1];
        a += __shfl_xor_sync(FULL, a, 16);
        b += __shfl_xor_sync(FULL, b, 16);
        v8[i] = (lane & 16) ? b : a;
    }
    float v4[4];
#pragma unroll
    for (int i = 0; i < 4; i++) {
        float a = v8[2*i], b = v8[2*i+1];
        a += __shfl_xor_sync(FULL, a, 8);
        b += __shfl_xor_sync(FULL, b, 8);
        v4[i] = (lane & 8) ? b : a;
    }
    float v2[2];
#pragma unroll
    for (int i = 0; i < 2; i++) {
        float a = v4[2*i], b = v4[2*i+1];
        a += __shfl_xor_sync(FULL, a, 4);
        b += __shfl_xor_sync(FULL, b, 4);
        v2[i] = (lane & 4) ? b : a;
    }
    float y;
    {
        float a = v2[0], b = v2[1];
        a += __shfl_xor_sync(FULL, a, 2);
        b += __shfl_xor_sync(FULL, b, 2);
        y = (lane & 2) ? b : a;
    }
    y += __shfl_xor_sync(FULL, y, 1);

    // Cross-warp combine: warp h=0 publishes, warp h=1 finishes.
    if (h == 0) red[team * 32 + lane] = y;
    __syncthreads();

    if (h == 1) {
        y += red[team * 32 + lane];

        const int nl = ((lane >> 4) & 1) | ((lane >> 2) & 2)
                     | (lane & 4) | ((lane << 2) & 8);
        const float S = y * __shfl_sync(FULL, stepv, nl);

        // Lane-parallel softmax (each of 16 values duplicated 2x).
        float mx = S;
        mx = fmaxf(mx, __shfl_xor_sync(FULL, mx, 16));
        mx = fmaxf(mx, __shfl_xor_sync(FULL, mx, 8));
        mx = fmaxf(mx, __shfl_xor_sync(FULL, mx, 4));
        mx = fmaxf(mx, __shfl_xor_sync(FULL, mx, 2));
        mx = fmaxf(mx, __shfl_xor_sync(FULL, mx, 1));

        float e = __expf((S - mx) * 10.0f);
        float tot = e;
        tot += __shfl_xor_sync(FULL, tot, 16);
        tot += __shfl_xor_sync(FULL, tot, 8);
        tot += __shfl_xor_sync(FULL, tot, 4);
        tot += __shfl_xor_sync(FULL, tot, 2);
        tot += __shfl_xor_sync(FULL, tot, 1);   // = 2 * denom

        if (lane == 0)                           // n(0) = 0: the positive
            out[gw] = e * 2.0f / tot;
    }
}

// ---------------------------------------------------------------------------
// Host-side exact replication of numpy's
//   np.random.default_rng(0).choice(np.arange(1, 8192), size=15, replace=False)
// SeedSequence(0) -> PCG64 (XSL-RR 128/64) -> Generator.choice Floyd's algorithm
// with hash set + final _shuffle_int. Deterministic, stateless, no allocation.
// ---------------------------------------------------------------------------
namespace ibns_rng {

typedef unsigned __int128 u128;

struct Pcg {
    u128 state, inc;
    int has32;
    uint32_t buf;
};

static inline uint64_t rotr64(uint64_t x, uint32_t r) {
    return (x >> r) | (x << ((64u - r) & 63u));
}

static const u128 PCG_MULT = (((u128)2549297995355413924ULL) << 64) | 4865540595714422341ULL;

static inline uint64_t pcg_next64(Pcg* p) {
    p->state = p->state * PCG_MULT + p->inc;
    uint64_t hi = (uint64_t)(p->state >> 64);
    uint64_t lo = (uint64_t)p->state;
    uint32_t rot = (uint32_t)(p->state >> 122);
    return rotr64(hi ^ lo, rot);
}

static inline uint32_t pcg_next32(Pcg* p) {
    if (p->has32) { p->has32 = 0; return p->buf; }
    uint64_t v = pcg_next64(p);
    p->has32 = 1;
    p->buf = (uint32_t)(v >> 32);
    return (uint32_t)v;
}

static inline uint32_t lemire32(Pcg* p, uint32_t rng) {
    if (rng == 0) return 0;
    const uint32_t rng_excl = rng + 1u;
    uint64_t m = (uint64_t)pcg_next32(p) * (uint64_t)rng_excl;
    uint32_t leftover = (uint32_t)m;
    if (leftover < rng_excl) {
        const uint32_t threshold = (0xFFFFFFFFu - rng) % rng_excl;
        while (leftover < threshold) {
            m = (uint64_t)pcg_next32(p) * (uint64_t)rng_excl;
            leftover = (uint32_t)m;
        }
    }
    return (uint32_t)(m >> 32);
}

static const uint32_t INIT_A = 0x43b0d7e5u, MULT_A = 0x931e8875u;
static const uint32_t INIT_B = 0x8b51f9ddu, MULT_B = 0x58f38dedu;
static const uint32_t MIX_L  = 0xca01f9ddu, MIX_R  = 0x4973f715u;

static inline uint32_t hashmix(uint32_t v, uint32_t* hc) {
    v ^= *hc;
    *hc = (uint32_t)(*hc * MULT_A);
    v = (uint32_t)(v * *hc);
    v ^= v >> 16;
    return v;
}
static inline uint32_t mixfn(uint32_t x, uint32_t y) {
    uint32_t r = (uint32_t)(MIX_L * x - MIX_R * y);
    r ^= r >> 16;
    return r;
}

static void compute_offsets(int* off16) {
    uint32_t pool[4];
    uint32_t hc = INIT_A;
    pool[0] = hashmix(0u, &hc);
    pool[1] = hashmix(0u, &hc);
    pool[2] = hashmix(0u, &hc);
    pool[3] = hashmix(0u, &hc);
    for (int i_src = 0; i_src < 4; i_src++)
        for (int i_dst = 0; i_dst < 4; i_dst++)
            if (i_src != i_dst)
                pool[i_dst] = mixfn(pool[i_dst], hashmix(pool[i_src], &hc));

    uint32_t w[8];
    hc = INIT_B;
    for (int i = 0; i < 8; i++) {
        uint32_t dv = pool[i & 3];
        dv ^= hc;
        hc = (uint32_t)(hc * MULT_B);
        dv = (uint32_t)(dv * hc);
        dv ^= dv >> 16;
        w[i] = dv;
    }
    uint64_t val[4];
    for (int k = 0; k < 4; k++)
        val[k] = (uint64_t)w[2 * k] | ((uint64_t)w[2 * k + 1] << 32);

    u128 initstate = (((u128)val[0]) << 64) | val[1];
    u128 initseq   = (((u128)val[2]) << 64) | val[3];
    Pcg p;
    p.has32 = 0; p.buf = 0;
    p.state = 0;
    p.inc = (initseq << 1) | 1;
    p.state = p.state * PCG_MULT + p.inc;
    p.state += initstate;
    p.state = p.state * PCG_MULT + p.inc;

    const int pop_size = 8191, size = 15;
    const uint64_t NONE = ~(uint64_t)0;
    uint64_t hset[32];
    for (int i = 0; i < 32; i++) hset[i] = NONE;
    int64_t idx[15];
    for (int j = pop_size - size; j < pop_size; j++) {
        uint64_t v = (uint64_t)lemire32(&p, (uint32_t)j);
        uint32_t loc = (uint32_t)(v & 31u);
        while (hset[loc] != NONE && hset[loc] != v) loc = (loc + 1u) & 31u;
        if (hset[loc] == NONE) {
            hset[loc] = v;
            idx[j - (pop_size - size)] = (int64_t)v;
        } else {
            loc = (uint32_t)((uint32_t)j & 31u);
            while (hset[loc] != NONE) loc = (loc + 1u) & 31u;
            hset[loc] = (uint64_t)j;
            idx[j - (pop_size - size)] = (int64_t)j;
        }
    }
    for (int i = size - 1; i >= 1; i--) {
        uint32_t j = lemire32(&p, (uint32_t)i);
        int64_t t = idx[j]; idx[j] = idx[i]; idx[i] = t;
    }

    off16[0] = 0;
    for (int n = 0; n < 15; n++) off16[n + 1] = (int)(idx[n] + 1);
}

} // namespace ibns_rng

extern "C" void kernel_launch(void* const* d_in, const int* in_sizes, int n_in,
                              void* d_out, int out_size) {
    (void)in_sizes; (void)n_in; (void)out_size;
    OffArgs oa;
    ibns_rng::compute_offsets(oa.off);

    const float* q     = (const float*)d_in[0];
    const float* items = (const float*)d_in[1];
    float* out         = (float*)d_out;

    // Pack (primary): single-wave grid, all CTAs resident at once, trigger at
    // CTA start -> main can co-reside and overlap its q-phase with packing.
    ibns_pack_kernel<<<PACK_CTAS, 256>>>(items);

    // Main (secondary) with Programmatic Dependent Launch.
    cudaLaunchConfig_t cfg = {};
    cfg.gridDim  = dim3(B_ROWS / 4);
    cfg.blockDim = dim3(256);
    cfg.dynamicSmemBytes = 0;
    cfg.stream = 0;
    cudaLaunchAttribute attr[1];
    attr[0].id = cudaLaunchAttributeProgrammaticStreamSerialization;
    attr[0].val.programmaticStreamSerializationAllowed = 1;
    cfg.attrs = attr;
    cfg.numAttrs = 1;
    cudaError_t e = cudaLaunchKernelEx(&cfg, ibns_kernel, q, out, oa);
    if (e != cudaSuccess) {
        // Fallback: plain serialized launch (still correct).
        ibns_kernel<<<B_ROWS / 4, 256>>>(q, out, oa);
    }
}